// round 1
// baseline (speedup 1.0000x reference)
#include <cuda_runtime.h>
#include <cuda_bf16.h>
#include <cstdint>

#define VOCAB 20000
#define D     512
#define B     64
#define S     256
#define C     16
#define G4D   (4*D)      // 2048

// ---------------- scratch (device globals; no allocation allowed) ----------
__device__ float g_x[S*B*D];        // [s][b][d]  == row-major [16384][512]
__device__ float g_gx[S*B*G4D];     // [s][b][4D] == row-major [16384][2048]
__device__ float g_h[B*D];
__device__ float g_final[B*D];
__device__ unsigned int g_arrive;

// ---------------- helpers ---------------------------------------------------
__device__ __forceinline__ float cvt_tf32(float x) {
    uint32_t u;
    asm("cvt.rna.tf32.f32 %0, %1;" : "=r"(u) : "f"(x));
    return __uint_as_float(u);
}

__device__ __forceinline__ void mma_tf32(float* c, const uint32_t* a, const uint32_t* b) {
    asm volatile(
        "mma.sync.aligned.m16n8k8.row.col.f32.tf32.tf32.f32 "
        "{%0,%1,%2,%3}, {%4,%5,%6,%7}, {%8,%9}, {%0,%1,%2,%3};"
        : "+f"(c[0]), "+f"(c[1]), "+f"(c[2]), "+f"(c[3])
        : "r"(a[0]), "r"(a[1]), "r"(a[2]), "r"(a[3]),
          "r"(b[0]), "r"(b[1]));
}

// packed fp32x2 FMA (Blackwell): acc.lo += a.lo*b.lo ; acc.hi += a.hi*b.hi
__device__ __forceinline__ void fma2(unsigned long long& acc,
                                     unsigned long long a, unsigned long long b) {
    asm("fma.rn.f32x2 %0, %1, %2, %0;" : "+l"(acc) : "l"(a), "l"(b));
}

__device__ __forceinline__ float red2(unsigned long long a) {
    return __uint_as_float((unsigned)a) + __uint_as_float((unsigned)(a >> 32));
}

// ---------------- K1: embedding gather + sum over codes ---------------------
__global__ void k1_embed(const int* __restrict__ seqs, const float* __restrict__ emb) {
    __shared__ int sidx[C];
    int bs  = blockIdx.x;            // bs = b*256 + s
    int tid = threadIdx.x;           // 128 threads, each one float4 of D
    if (tid < C) sidx[tid] = seqs[bs * C + tid];
    __syncthreads();
    int b = bs >> 8, s = bs & 255;
    float4 acc = make_float4(0.f, 0.f, 0.f, 0.f);
#pragma unroll
    for (int c = 0; c < C; c++) {
        int idx = sidx[c];
        if (idx != VOCAB) {
            float4 v = __ldg(((const float4*)(emb + (size_t)idx * D)) + tid);
            acc.x += v.x; acc.y += v.y; acc.z += v.z; acc.w += v.w;
        }
    }
    *(((float4*)(g_x + (size_t)(s * B + b) * D)) + tid) = acc;
}

// ---------------- K2: gates_x = x @ w_ih^T  (tf32 mma) -----------------------
// C[m][n] = sum_k A[m][k] * W[n][k]; A=g_x [16384][512], W=w_ih [2048][512]
// Block tile 128x128, BK=32, 8 warps (2 in m x 4 in n), warp tile 64x32.
__global__ void __launch_bounds__(256) k2_gemm(const float* __restrict__ Bw) {
    __shared__ float As[128][36];   // [m][k], pad 36 -> conflict-free
    __shared__ float Bs[128][36];   // [n][k]

    int tid  = threadIdx.x;
    int warp = tid >> 5, lane = tid & 31;
    int g    = lane >> 2, tig = lane & 3;
    int wm   = (warp & 1) * 64;     // warp m offset
    int wn   = (warp >> 1) * 32;    // warp n offset
    int bm0  = blockIdx.y * 128;
    int bn0  = blockIdx.x * 128;

    float acc[4][4][4];
#pragma unroll
    for (int mt = 0; mt < 4; mt++)
#pragma unroll
        for (int nt = 0; nt < 4; nt++)
#pragma unroll
            for (int r = 0; r < 4; r++) acc[mt][nt][r] = 0.f;

    for (int kt = 0; kt < D; kt += 32) {
        // load A and B tiles (128 rows x 32 cols each), cvt to tf32
#pragma unroll
        for (int i = 0; i < 4; i++) {
            int f   = tid + i * 256;          // 0..1023 float4 slots
            int row = f >> 3, cc = f & 7;
            float4 v = *(const float4*)(g_x + (size_t)(bm0 + row) * D + kt + cc * 4);
            float4 cv = make_float4(cvt_tf32(v.x), cvt_tf32(v.y), cvt_tf32(v.z), cvt_tf32(v.w));
            *(float4*)&As[row][cc * 4] = cv;
            float4 w = *(const float4*)(Bw + (size_t)(bn0 + row) * D + kt + cc * 4);
            float4 cw = make_float4(cvt_tf32(w.x), cvt_tf32(w.y), cvt_tf32(w.z), cvt_tf32(w.w));
            *(float4*)&Bs[row][cc * 4] = cw;
        }
        __syncthreads();

#pragma unroll
        for (int ks = 0; ks < 4; ks++) {
            int k0 = ks * 8;
            uint32_t af[4][4], bf[4][2];
#pragma unroll
            for (int mt = 0; mt < 4; mt++) {
                int m = wm + mt * 16;
                af[mt][0] = __float_as_uint(As[m + g    ][k0 + tig    ]);
                af[mt][1] = __float_as_uint(As[m + g + 8][k0 + tig    ]);
                af[mt][2] = __float_as_uint(As[m + g    ][k0 + tig + 4]);
                af[mt][3] = __float_as_uint(As[m + g + 8][k0 + tig + 4]);
            }
#pragma unroll
            for (int nt = 0; nt < 4; nt++) {
                int n = wn + nt * 8;
                bf[nt][0] = __float_as_uint(Bs[n + g][k0 + tig    ]);
                bf[nt][1] = __float_as_uint(Bs[n + g][k0 + tig + 4]);
            }
#pragma unroll
            for (int mt = 0; mt < 4; mt++)
#pragma unroll
                for (int nt = 0; nt < 4; nt++)
                    mma_tf32(acc[mt][nt], af[mt], bf[nt]);
        }
        __syncthreads();
    }

    // epilogue
#pragma unroll
    for (int mt = 0; mt < 4; mt++) {
#pragma unroll
        for (int nt = 0; nt < 4; nt++) {
            int m0 = bm0 + wm + mt * 16 + g;
            int n0 = bn0 + wn + nt * 8 + 2 * tig;
            *(float2*)&g_gx[(size_t)m0 * G4D + n0] =
                make_float2(acc[mt][nt][0], acc[mt][nt][1]);
            *(float2*)&g_gx[(size_t)(m0 + 8) * G4D + n0] =
                make_float2(acc[mt][nt][2], acc[mt][nt][3]);
        }
    }
}

// ---------------- Kreset: zero the grid-barrier counter ----------------------
__global__ void k_reset() { g_arrive = 0u; }

// ---------------- K3: persistent LSTM recurrence (fp32, f32x2 FMA) ----------
// 128 CTAs x 256 threads. CTA owns d in [bid*4, bid*4+4); thread = (b, dd).
// w_hh slice (16 rows) pinned in SMEM; h broadcast via L2 (__ldcg) each step.
#define WPAD 516
__global__ void __launch_bounds__(256) k3_lstm(const float* __restrict__ whh,
                                               const int*   __restrict__ lengths) {
    __shared__ float w_sh[16 * WPAD];
    int tid = threadIdx.x, bid = blockIdx.x;
    int d0  = bid * 4;

#pragma unroll
    for (int r = 0; r < 16; r++) {
        int gate = r >> 2, dd = r & 3;
        int row = gate * D + d0 + dd;
#pragma unroll
        for (int k = tid; k < D; k += 256)
            w_sh[r * WPAD + k] = whh[(size_t)row * D + k];
    }
    int b = tid >> 2, dd = tid & 3, d = d0 + dd;
    int mylen = lengths[b];
    __syncthreads();

    const ulonglong2* hp  = (const ulonglong2*)(g_h + b * D);
    const ulonglong2* w0p = (const ulonglong2*)(w_sh + (0  + dd) * WPAD);
    const ulonglong2* w1p = (const ulonglong2*)(w_sh + (4  + dd) * WPAD);
    const ulonglong2* w2p = (const ulonglong2*)(w_sh + (8  + dd) * WPAD);
    const ulonglong2* w3p = (const ulonglong2*)(w_sh + (12 + dd) * WPAD);

    float c = 0.f;
    for (int t = 0; t < S; t++) {
        float s0 = 0.f, s1 = 0.f, s2 = 0.f, s3 = 0.f;
        if (t > 0) {
            unsigned long long a0 = 0, a1 = 0, a2 = 0, a3 = 0,
                               a4 = 0, a5 = 0, a6 = 0, a7 = 0;
#pragma unroll 8
            for (int kk = 0; kk < D / 4; kk++) {
                ulonglong2 hv  = __ldcg(hp + kk);     // L2 read (L1 is stale!)
                ulonglong2 wv0 = w0p[kk];
                ulonglong2 wv1 = w1p[kk];
                ulonglong2 wv2 = w2p[kk];
                ulonglong2 wv3 = w3p[kk];
                fma2(a0, hv.x, wv0.x); fma2(a1, hv.y, wv0.y);
                fma2(a2, hv.x, wv1.x); fma2(a3, hv.y, wv1.y);
                fma2(a4, hv.x, wv2.x); fma2(a5, hv.y, wv2.y);
                fma2(a6, hv.x, wv3.x); fma2(a7, hv.y, wv3.y);
            }
            s0 = red2(a0) + red2(a1);
            s1 = red2(a2) + red2(a3);
            s2 = red2(a4) + red2(a5);
            s3 = red2(a6) + red2(a7);
        }
        int base = (t * B + b) * G4D + d;
        float gi = __ldg(g_gx + base)           + s0;
        float gf = __ldg(g_gx + base + D)       + s1;
        float gg = __ldg(g_gx + base + 2 * D)   + s2;
        float go = __ldg(g_gx + base + 3 * D)   + s3;

        float iv = 1.f / (1.f + __expf(-gi));
        float fv = 1.f / (1.f + __expf(-gf));
        float gv = tanhf(gg);
        float ov = 1.f / (1.f + __expf(-go));
        c = fv * c + iv * gv;
        float h = ov * tanhf(c);

        g_h[b * D + d] = h;
        if (t == mylen - 1) g_final[b * D + d] = h;

        // ---- grid barrier (all 128 CTAs are co-resident: 1/SM, 128 <= 148)
        __syncthreads();
        if (tid == 0) {
            __threadfence();
            atomicAdd(&g_arrive, 1u);
            unsigned target = (unsigned)(t + 1) * (unsigned)gridDim.x;
            while (*(volatile unsigned*)&g_arrive < target) { }
            __threadfence();
        }
        __syncthreads();
    }
}

// ---------------- K4: out = final @ w_out^T + b_out --------------------------
__global__ void k4_out(const float* __restrict__ wout, const float* __restrict__ bout,
                       float* __restrict__ out) {
    int b = blockIdx.x;
    int tid = threadIdx.x;           // 64 threads: warp 0 -> o=0, warp 1 -> o=1
    int o = tid >> 5, lane = tid & 31;
    float s = 0.f;
    for (int k = lane; k < D; k += 32)
        s += g_final[b * D + k] * wout[o * D + k];
#pragma unroll
    for (int off = 16; off; off >>= 1)
        s += __shfl_down_sync(0xffffffffu, s, off);
    if (lane == 0) out[b * 2 + o] = s + bout[o];
}

// ---------------- launcher ---------------------------------------------------
extern "C" void kernel_launch(void* const* d_in, const int* in_sizes, int n_in,
                              void* d_out, int out_size) {
    const int*   seqs    = (const int*)  d_in[0];
    const int*   lengths = (const int*)  d_in[1];
    const float* emb     = (const float*)d_in[2];
    const float* w_ih    = (const float*)d_in[3];
    const float* w_hh    = (const float*)d_in[4];
    const float* w_out   = (const float*)d_in[5];
    const float* b_out   = (const float*)d_in[6];
    float*       out     = (float*)d_out;

    k1_embed<<<B * S, 128>>>(seqs, emb);
    dim3 g2(G4D / 128, (B * S) / 128);   // (16, 128)
    k2_gemm<<<g2, 256>>>(w_ih);
    k_reset<<<1, 1>>>();
    k3_lstm<<<128, 256>>>(w_hh, lengths);
    k4_out<<<B, 64>>>(w_out, b_out, out);
}

// round 4
// speedup vs baseline: 1.1835x; 1.1835x over previous
#include <cuda_runtime.h>
#include <cuda_bf16.h>
#include <cstdint>

#define VOCAB 20000
#define D     512
#define B     64
#define S     256
#define C     16
#define G4D   (4*D)      // 2048

// ---------------- scratch (device globals; no allocation allowed) ----------
__device__ float g_x[S*B*D];        // [s][b][d]
__device__ float g_gx[S*B*G4D];     // [s][b][4D]
__device__ float g_h[B*D];
__device__ float g_final[B*D];
__device__ unsigned int g_arrive;

// ---------------- helpers ---------------------------------------------------
__device__ __forceinline__ float cvt_tf32(float x) {
    uint32_t u;
    asm("cvt.rna.tf32.f32 %0, %1;" : "=r"(u) : "f"(x));
    return __uint_as_float(u);
}

__device__ __forceinline__ void mma_tf32(float* c, const uint32_t* a, const uint32_t* b) {
    asm volatile(
        "mma.sync.aligned.m16n8k8.row.col.f32.tf32.tf32.f32 "
        "{%0,%1,%2,%3}, {%4,%5,%6,%7}, {%8,%9}, {%0,%1,%2,%3};"
        : "+f"(c[0]), "+f"(c[1]), "+f"(c[2]), "+f"(c[3])
        : "r"(a[0]), "r"(a[1]), "r"(a[2]), "r"(a[3]),
          "r"(b[0]), "r"(b[1]));
}

// packed fp32x2 FMA (Blackwell): acc.lo += a.lo*b.lo ; acc.hi += a.hi*b.hi
__device__ __forceinline__ void fma2(unsigned long long& acc,
                                     unsigned long long a, unsigned long long b) {
    asm("fma.rn.f32x2 %0, %1, %2, %0;" : "+l"(acc) : "l"(a), "l"(b));
}

__device__ __forceinline__ float red2(unsigned long long a) {
    return __uint_as_float((unsigned)a) + __uint_as_float((unsigned)(a >> 32));
}

template<int N> __device__ __forceinline__ void cpwait() {
    asm volatile("cp.async.wait_group %0;" :: "n"(N) : "memory");
}
__device__ __forceinline__ void cpasync16(uint32_t dst, const void* src) {
    asm volatile("cp.async.cg.shared.global [%0], [%1], 16;" :: "r"(dst), "l"(src) : "memory");
}
__device__ __forceinline__ void cpcommit() {
    asm volatile("cp.async.commit_group;" ::: "memory");
}

// ---------------- K1: embedding gather + sum over codes ---------------------
__global__ void k1_embed(const int* __restrict__ seqs, const float* __restrict__ emb) {
    __shared__ int sidx[C];
    int bs  = blockIdx.x;
    int tid = threadIdx.x;
    if (tid < C) sidx[tid] = seqs[bs * C + tid];
    __syncthreads();
    int b = bs >> 8, s = bs & 255;
    float4 acc = make_float4(0.f, 0.f, 0.f, 0.f);
#pragma unroll
    for (int c = 0; c < C; c++) {
        int idx = sidx[c];
        if (idx != VOCAB) {
            float4 v = __ldg(((const float4*)(emb + (size_t)idx * D)) + tid);
            acc.x += v.x; acc.y += v.y; acc.z += v.z; acc.w += v.w;
        }
    }
    *(((float4*)(g_x + (size_t)(s * B + b) * D)) + tid) = acc;
}

// ---------------- K2: gates_x = x @ w_ih^T  (tf32 mma) -----------------------
__global__ void __launch_bounds__(256) k2_gemm(const float* __restrict__ Bw) {
    __shared__ float As[128][36];
    __shared__ float Bs[128][36];

    int tid  = threadIdx.x;
    int warp = tid >> 5, lane = tid & 31;
    int g    = lane >> 2, tig = lane & 3;
    int wm   = (warp & 1) * 64;
    int wn   = (warp >> 1) * 32;
    int bm0  = blockIdx.y * 128;
    int bn0  = blockIdx.x * 128;

    float acc[4][4][4];
#pragma unroll
    for (int mt = 0; mt < 4; mt++)
#pragma unroll
        for (int nt = 0; nt < 4; nt++)
#pragma unroll
            for (int r = 0; r < 4; r++) acc[mt][nt][r] = 0.f;

    for (int kt = 0; kt < D; kt += 32) {
#pragma unroll
        for (int i = 0; i < 4; i++) {
            int f   = tid + i * 256;
            int row = f >> 3, cc = f & 7;
            float4 v = *(const float4*)(g_x + (size_t)(bm0 + row) * D + kt + cc * 4);
            float4 cv = make_float4(cvt_tf32(v.x), cvt_tf32(v.y), cvt_tf32(v.z), cvt_tf32(v.w));
            *(float4*)&As[row][cc * 4] = cv;
            float4 w = *(const float4*)(Bw + (size_t)(bn0 + row) * D + kt + cc * 4);
            float4 cw = make_float4(cvt_tf32(w.x), cvt_tf32(w.y), cvt_tf32(w.z), cvt_tf32(w.w));
            *(float4*)&Bs[row][cc * 4] = cw;
        }
        __syncthreads();

#pragma unroll
        for (int ks = 0; ks < 4; ks++) {
            int k0 = ks * 8;
            uint32_t af[4][4], bf[4][2];
#pragma unroll
            for (int mt = 0; mt < 4; mt++) {
                int m = wm + mt * 16;
                af[mt][0] = __float_as_uint(As[m + g    ][k0 + tig    ]);
                af[mt][1] = __float_as_uint(As[m + g + 8][k0 + tig    ]);
                af[mt][2] = __float_as_uint(As[m + g    ][k0 + tig + 4]);
                af[mt][3] = __float_as_uint(As[m + g + 8][k0 + tig + 4]);
            }
#pragma unroll
            for (int nt = 0; nt < 4; nt++) {
                int n = wn + nt * 8;
                bf[nt][0] = __float_as_uint(Bs[n + g][k0 + tig    ]);
                bf[nt][1] = __float_as_uint(Bs[n + g][k0 + tig + 4]);
            }
#pragma unroll
            for (int mt = 0; mt < 4; mt++)
#pragma unroll
                for (int nt = 0; nt < 4; nt++)
                    mma_tf32(acc[mt][nt], af[mt], bf[nt]);
        }
        __syncthreads();
    }

#pragma unroll
    for (int mt = 0; mt < 4; mt++) {
#pragma unroll
        for (int nt = 0; nt < 4; nt++) {
            int m0 = bm0 + wm + mt * 16 + g;
            int n0 = bn0 + wn + nt * 8 + 2 * tig;
            *(float2*)&g_gx[(size_t)m0 * G4D + n0] =
                make_float2(acc[mt][nt][0], acc[mt][nt][1]);
            *(float2*)&g_gx[(size_t)(m0 + 8) * G4D + n0] =
                make_float2(acc[mt][nt][2], acc[mt][nt][3]);
        }
    }
}

// ---------------- Kreset ------------------------------------------------------
__global__ void k_reset() { g_arrive = 0u; }

// ---------------- K3: persistent LSTM recurrence ------------------------------
// 128 CTAs x 256 threads. CTA owns dims [bid*4, bid*4+4) x 4 gates = 16 rows.
// Weights live in REGISTERS (32 floats/thread). h is staged GMEM->SMEM each
// step via cp.async.cg (XOR-swizzled), read with warp-broadcast LDS.128.
// Dot thread = (row = tid>>4, ks = tid&15); pointwise thread = (b=tid>>2, dd=tid&3).
extern __shared__ char k3_smem[];

__global__ void __launch_bounds__(256) k3_lstm(const float* __restrict__ whh,
                                               const int*   __restrict__ lengths) {
    float* s_h = (float*)k3_smem;                     // 131072 B, swizzled [64][512]
    float* s_g = (float*)(k3_smem + 131072);          // [16][64]
    uint32_t s_h_u32 = (uint32_t)__cvta_generic_to_shared(s_h);

    int tid = threadIdx.x, bid = blockIdx.x;
    int d0  = bid * 4;
    int row = tid >> 4;        // 0..15: gate = row>>2, dd = row&3
    int ks  = tid & 15;        // k-slice of 32

    // ---- weights into registers: w[row][ks*32 .. +32] as 16 packed pairs
    unsigned long long wreg[16];
    {
        int gate = row >> 2, dd = row & 3;
        const float4* wp = (const float4*)(whh + (size_t)(gate * D + d0 + dd) * D + ks * 32);
#pragma unroll
        for (int i = 0; i < 8; i++) {
            float4 v = __ldg(wp + i);
            wreg[2*i]   = ((unsigned long long)__float_as_uint(v.y) << 32) | __float_as_uint(v.x);
            wreg[2*i+1] = ((unsigned long long)__float_as_uint(v.w) << 32) | __float_as_uint(v.z);
        }
    }
    int pb = tid >> 2, pdd = tid & 3, pd = d0 + pdd;
    int mylen = lengths[pb];
    float c = 0.f;

    const char* s_h_bytes = (const char*)s_h;

    for (int t = 0; t < S; t++) {
        // prefetch this step's input-projection gates (independent of h)
        size_t gxbase = ((size_t)(t * B + pb)) * G4D + pd;
        float gi = __ldg(g_gx + gxbase);
        float gf = __ldg(g_gx + gxbase + D);
        float gg = __ldg(g_gx + gxbase + 2 * D);
        float go = __ldg(g_gx + gxbase + 3 * D);

        float sg0 = 0.f, sg1 = 0.f, sg2 = 0.f, sg3 = 0.f;
        if (t > 0) {
            // ---- stage h: 8192 x 16B chunks, 4 commit groups of 16 batches
#pragma unroll
            for (int grp = 0; grp < 4; grp++) {
#pragma unroll
                for (int jj = 0; jj < 8; jj++) {
                    int j   = grp * 8 + jj;
                    int idx = tid + 256 * j;              // chunk id
                    int b   = idx >> 7, cch = idx & 127;
                    int sc  = cch ^ ((cch >> 3) & 7);     // XOR swizzle
                    cpasync16(s_h_u32 + b * 2048 + sc * 16,
                              (const char*)g_h + (size_t)idx * 16);
                }
                cpcommit();
            }

            // ---- dot product over 4 pipelined b-blocks of 16
            auto dotblock = [&](int b0) {
#pragma unroll 4
                for (int bb = 0; bb < 16; bb++) {
                    int b = b0 + bb;
                    const char* hb = s_h_bytes + b * 2048 + ks * 128;
                    unsigned long long a0 = 0, a1 = 0;
#pragma unroll
                    for (int i = 0; i < 8; i++) {
                        int off = (i ^ (ks & 7)) * 16;
                        ulonglong2 hv = *(const ulonglong2*)(hb + off);
                        fma2(a0, hv.x, wreg[2*i]);
                        fma2(a1, hv.y, wreg[2*i+1]);
                    }
                    float s = red2(a0) + red2(a1);
                    s += __shfl_xor_sync(0xffffffffu, s, 1);
                    s += __shfl_xor_sync(0xffffffffu, s, 2);
                    s += __shfl_xor_sync(0xffffffffu, s, 4);
                    s += __shfl_xor_sync(0xffffffffu, s, 8);
                    if (ks == 0) s_g[row * 64 + b] = s;
                }
            };
            cpwait<3>(); __syncthreads(); dotblock(0);
            cpwait<2>(); __syncthreads(); dotblock(16);
            cpwait<1>(); __syncthreads(); dotblock(32);
            cpwait<0>(); __syncthreads(); dotblock(48);
            __syncthreads();
            sg0 = s_g[(0 * 4 + pdd) * 64 + pb];
            sg1 = s_g[(1 * 4 + pdd) * 64 + pb];
            sg2 = s_g[(2 * 4 + pdd) * 64 + pb];
            sg3 = s_g[(3 * 4 + pdd) * 64 + pb];
        }

        // ---- pointwise LSTM cell for (pb, pd)
        float iv = 1.f / (1.f + __expf(-(gi + sg0)));
        float fv = 1.f / (1.f + __expf(-(gf + sg1)));
        float gv = tanhf(gg + sg2);
        float ov = 1.f / (1.f + __expf(-(go + sg3)));
        c = fv * c + iv * gv;
        float h = ov * tanhf(c);

        g_h[pb * D + pd] = h;
        if (t == mylen - 1) g_final[pb * D + pd] = h;

        // ---- grid barrier (128 CTAs co-resident, 1/SM)
        __syncthreads();
        if (tid == 0) {
            __threadfence();
            atomicAdd(&g_arrive, 1u);
            unsigned target = (unsigned)(t + 1) * 128u;
            while (*(volatile unsigned*)&g_arrive < target) { }
            __threadfence();
        }
        __syncthreads();
    }
}

// ---------------- K4: out = final @ w_out^T + b_out --------------------------
__global__ void k4_out(const float* __restrict__ wout, const float* __restrict__ bout,
                       float* __restrict__ out) {
    int b = blockIdx.x;
    int tid = threadIdx.x;
    int o = tid >> 5, lane = tid & 31;
    float s = 0.f;
    for (int k = lane; k < D; k += 32)
        s += g_final[b * D + k] * wout[o * D + k];
#pragma unroll
    for (int off = 16; off; off >>= 1)
        s += __shfl_down_sync(0xffffffffu, s, off);
    if (lane == 0) out[b * 2 + o] = s + bout[o];
}

// ---------------- launcher ---------------------------------------------------
extern "C" void kernel_launch(void* const* d_in, const int* in_sizes, int n_in,
                              void* d_out, int out_size) {
    const int*   seqs    = (const int*)  d_in[0];
    const int*   lengths = (const int*)  d_in[1];
    const float* emb     = (const float*)d_in[2];
    const float* w_ih    = (const float*)d_in[3];
    const float* w_hh    = (const float*)d_in[4];
    const float* w_out   = (const float*)d_in[5];
    const float* b_out   = (const float*)d_in[6];
    float*       out     = (float*)d_out;

    k1_embed<<<B * S, 128>>>(seqs, emb);
    dim3 g2(G4D / 128, (B * S) / 128);   // (16, 128)
    k2_gemm<<<g2, 256>>>(w_ih);
    k_reset<<<1, 1>>>();

    const int K3_SMEM = 131072 + 16 * 64 * 4;   // 135168 B
    cudaFuncSetAttribute(k3_lstm, cudaFuncAttributeMaxDynamicSharedMemorySize, K3_SMEM);
    k3_lstm<<<128, 256, K3_SMEM>>>(w_hh, lengths);

    k4_out<<<B, 64>>>(w_out, b_out, out);
}

// round 7
// speedup vs baseline: 1.7428x; 1.4725x over previous
#include <cuda_runtime.h>
#include <cuda_bf16.h>
#include <cstdint>

#define VOCAB 20000
#define D     512
#define B     64
#define S     256
#define C     16
#define G4D   (4*D)      // 2048

// ---------------- scratch (device globals; no allocation allowed) ----------
__device__ float g_x[S*B*D];        // [s][b][d]
__device__ float g_gx[S*B*G4D];     // [s][b][4D]
__device__ float g_h[B*D];
__device__ float g_final[B*D];
__device__ unsigned int g_arrive;

// ---------------- helpers ---------------------------------------------------
__device__ __forceinline__ float cvt_tf32(float x) {
    uint32_t u;
    asm("cvt.rna.tf32.f32 %0, %1;" : "=r"(u) : "f"(x));
    return __uint_as_float(u);
}

__device__ __forceinline__ void mma_tf32(float* c, const uint32_t* a, const uint32_t* b) {
    asm volatile(
        "mma.sync.aligned.m16n8k8.row.col.f32.tf32.tf32.f32 "
        "{%0,%1,%2,%3}, {%4,%5,%6,%7}, {%8,%9}, {%0,%1,%2,%3};"
        : "+f"(c[0]), "+f"(c[1]), "+f"(c[2]), "+f"(c[3])
        : "r"(a[0]), "r"(a[1]), "r"(a[2]), "r"(a[3]),
          "r"(b[0]), "r"(b[1]));
}

// packed fp32x2 FMA (Blackwell): acc.lo += a.lo*b.lo ; acc.hi += a.hi*b.hi
__device__ __forceinline__ void fma2(unsigned long long& acc,
                                     unsigned long long a, unsigned long long b) {
    asm("fma.rn.f32x2 %0, %1, %2, %0;" : "+l"(acc) : "l"(a), "l"(b));
}

__device__ __forceinline__ float red2(unsigned long long a) {
    return __uint_as_float((unsigned)a) + __uint_as_float((unsigned)(a >> 32));
}

template<int N> __device__ __forceinline__ void cpwait() {
    asm volatile("cp.async.wait_group %0;" :: "n"(N) : "memory");
}
__device__ __forceinline__ void cpasync16(uint32_t dst, const void* src) {
    asm volatile("cp.async.cg.shared.global [%0], [%1], 16;" :: "r"(dst), "l"(src) : "memory");
}
__device__ __forceinline__ void cpcommit() {
    asm volatile("cp.async.commit_group;" ::: "memory");
}

// ---------------- K1: embedding gather + sum over codes ---------------------
__global__ void k1_embed(const int* __restrict__ seqs, const float* __restrict__ emb) {
    __shared__ int sidx[C];
    int bs  = blockIdx.x;
    int tid = threadIdx.x;
    if (tid < C) sidx[tid] = seqs[bs * C + tid];
    __syncthreads();
    int b = bs >> 8, s = bs & 255;
    float4 acc = make_float4(0.f, 0.f, 0.f, 0.f);
#pragma unroll
    for (int c = 0; c < C; c++) {
        int idx = sidx[c];
        if (idx != VOCAB) {
            float4 v = __ldg(((const float4*)(emb + (size_t)idx * D)) + tid);
            acc.x += v.x; acc.y += v.y; acc.z += v.z; acc.w += v.w;
        }
    }
    *(((float4*)(g_x + (size_t)(s * B + b) * D)) + tid) = acc;
}

// ---------------- K2: gates_x = x @ w_ih^T  (tf32 mma) -----------------------
__global__ void __launch_bounds__(256) k2_gemm(const float* __restrict__ Bw) {
    __shared__ float As[128][36];
    __shared__ float Bs[128][36];

    int tid  = threadIdx.x;
    int warp = tid >> 5, lane = tid & 31;
    int g    = lane >> 2, tig = lane & 3;
    int wm   = (warp & 1) * 64;
    int wn   = (warp >> 1) * 32;
    int bm0  = blockIdx.y * 128;
    int bn0  = blockIdx.x * 128;

    float acc[4][4][4];
#pragma unroll
    for (int mt = 0; mt < 4; mt++)
#pragma unroll
        for (int nt = 0; nt < 4; nt++)
#pragma unroll
            for (int r = 0; r < 4; r++) acc[mt][nt][r] = 0.f;

    for (int kt = 0; kt < D; kt += 32) {
#pragma unroll
        for (int i = 0; i < 4; i++) {
            int f   = tid + i * 256;
            int row = f >> 3, cc = f & 7;
            float4 v = *(const float4*)(g_x + (size_t)(bm0 + row) * D + kt + cc * 4);
            float4 cv = make_float4(cvt_tf32(v.x), cvt_tf32(v.y), cvt_tf32(v.z), cvt_tf32(v.w));
            *(float4*)&As[row][cc * 4] = cv;
            float4 w = *(const float4*)(Bw + (size_t)(bn0 + row) * D + kt + cc * 4);
            float4 cw = make_float4(cvt_tf32(w.x), cvt_tf32(w.y), cvt_tf32(w.z), cvt_tf32(w.w));
            *(float4*)&Bs[row][cc * 4] = cw;
        }
        __syncthreads();

#pragma unroll
        for (int ks = 0; ks < 4; ks++) {
            int k0 = ks * 8;
            uint32_t af[4][4], bf[4][2];
#pragma unroll
            for (int mt = 0; mt < 4; mt++) {
                int m = wm + mt * 16;
                af[mt][0] = __float_as_uint(As[m + g    ][k0 + tig    ]);
                af[mt][1] = __float_as_uint(As[m + g + 8][k0 + tig    ]);
                af[mt][2] = __float_as_uint(As[m + g    ][k0 + tig + 4]);
                af[mt][3] = __float_as_uint(As[m + g + 8][k0 + tig + 4]);
            }
#pragma unroll
            for (int nt = 0; nt < 4; nt++) {
                int n = wn + nt * 8;
                bf[nt][0] = __float_as_uint(Bs[n + g][k0 + tig    ]);
                bf[nt][1] = __float_as_uint(Bs[n + g][k0 + tig + 4]);
            }
#pragma unroll
            for (int mt = 0; mt < 4; mt++)
#pragma unroll
                for (int nt = 0; nt < 4; nt++)
                    mma_tf32(acc[mt][nt], af[mt], bf[nt]);
        }
        __syncthreads();
    }

#pragma unroll
    for (int mt = 0; mt < 4; mt++) {
#pragma unroll
        for (int nt = 0; nt < 4; nt++) {
            int m0 = bm0 + wm + mt * 16 + g;
            int n0 = bn0 + wn + nt * 8 + 2 * tig;
            *(float2*)&g_gx[(size_t)m0 * G4D + n0] =
                make_float2(acc[mt][nt][0], acc[mt][nt][1]);
            *(float2*)&g_gx[(size_t)(m0 + 8) * G4D + n0] =
                make_float2(acc[mt][nt][2], acc[mt][nt][3]);
        }
    }
}

// ---------------- Kreset ------------------------------------------------------
__global__ void k_reset() { g_arrive = 0u; }

// ---------------- K3: persistent LSTM recurrence ------------------------------
// 128 CTAs x 256 threads. CTA owns dims [bid*4, bid*4+4) x 4 gates = 16 rows.
// Weights in registers (32 floats/thread). Lane mapping exploits SMEM
// broadcast: row = tid&15, ks = tid>>4 -> all 16 rows in a warp read the SAME
// h address (16-way broadcast). h staged GMEM->SMEM via pipelined cp.async.cg.
// Cross-warp k-reduction: shfl_xor(16) + s_part[b][warp][16 rows] + phase-2 sum.
extern __shared__ char k3_smem[];

__global__ void __launch_bounds__(256) k3_lstm(const float* __restrict__ whh,
                                               const int*   __restrict__ lengths) {
    float* s_h    = (float*)k3_smem;                       // [64][512]  131072 B
    float* s_part = (float*)(k3_smem + 131072);            // [64][8][16] 32768 B
    float* s_g    = (float*)(k3_smem + 131072 + 32768);    // [64][4][4]   4096 B
    uint32_t s_h_u32 = (uint32_t)__cvta_generic_to_shared(s_h);

    int tid = threadIdx.x, bid = blockIdx.x;
    int d0  = bid * 4;
    int row = tid & 15;        // row = gate*4 + dd
    int ks  = tid >> 4;        // 0..15: k-slice of 32 floats
    int w   = tid >> 5;        // warp id 0..7
    int lane = tid & 31;

    // ---- weights into registers: w[row][ks*32 .. +32] as 16 packed pairs
    unsigned long long wreg[16];
    {
        int gate = row >> 2, dd = row & 3;
        const float4* wp = (const float4*)(whh + (size_t)(gate * D + d0 + dd) * D + ks * 32);
#pragma unroll
        for (int i = 0; i < 8; i++) {
            float4 v = __ldg(wp + i);
            wreg[2*i]   = ((unsigned long long)__float_as_uint(v.y) << 32) | __float_as_uint(v.x);
            wreg[2*i+1] = ((unsigned long long)__float_as_uint(v.w) << 32) | __float_as_uint(v.z);
        }
    }
    int pb = tid >> 2, pdd = tid & 3, pd = d0 + pdd;
    int mylen = lengths[pb];
    float c = 0.f;

    for (int t = 0; t < S; t++) {
        // prefetch this step's input-projection gates (independent of h)
        size_t gxbase = ((size_t)(t * B + pb)) * G4D + pd;
        float gi = __ldg(g_gx + gxbase);
        float gf = __ldg(g_gx + gxbase + D);
        float gg = __ldg(g_gx + gxbase + 2 * D);
        float go = __ldg(g_gx + gxbase + 3 * D);

        float sg0 = 0.f, sg1 = 0.f, sg2 = 0.f, sg3 = 0.f;
        if (t > 0) {
            // ---- stage h: 8192 x 16B chunks (linear), 4 commit groups of 16 b
#pragma unroll
            for (int grp = 0; grp < 4; grp++) {
#pragma unroll
                for (int jj = 0; jj < 8; jj++) {
                    int idx = tid + 256 * (grp * 8 + jj);
                    cpasync16(s_h_u32 + idx * 16, (const char*)g_h + (size_t)idx * 16);
                }
                cpcommit();
            }

            // ---- dot over 4 pipelined b-blocks of 16
            auto dotblock = [&](int b0) {
#pragma unroll 2
                for (int bb = 0; bb < 16; bb++) {
                    int b = b0 + bb;
                    const ulonglong2* hp = (const ulonglong2*)(s_h + b * 512 + ks * 32);
                    unsigned long long a0 = 0, a1 = 0;
#pragma unroll
                    for (int i = 0; i < 8; i++) {
                        ulonglong2 hv = hp[i];           // 16-way broadcast
                        fma2(a0, hv.x, wreg[2*i]);
                        fma2(a1, hv.y, wreg[2*i+1]);
                    }
                    float s = red2(a0) + red2(a1);
                    s += __shfl_xor_sync(0xffffffffu, s, 16);  // combine warp's 2 k-halves
                    if (lane < 16)
                        s_part[b * 128 + w * 16 + row] = s;    // conflict-free 16 floats
                }
            };
            cpwait<3>(); __syncthreads(); dotblock(0);
            cpwait<2>(); __syncthreads(); dotblock(16);
            cpwait<1>(); __syncthreads(); dotblock(32);
            cpwait<0>(); __syncthreads(); dotblock(48);
            __syncthreads();

            // ---- phase 2: sum the 8 warp-partials; thread=(b2, gate)
            {
                int b2 = tid >> 2, gq = tid & 3;
                float4 a4 = make_float4(0.f, 0.f, 0.f, 0.f);
#pragma unroll
                for (int w2 = 0; w2 < 8; w2++) {
                    float4 v = *(const float4*)(s_part + b2 * 128 + w2 * 16 + gq * 4);
                    a4.x += v.x; a4.y += v.y; a4.z += v.z; a4.w += v.w;
                }
                *(float4*)(s_g + b2 * 16 + gq * 4) = a4;   // [b][gate][dd]
            }
            __syncthreads();
            sg0 = s_g[pb * 16 + 0  + pdd];
            sg1 = s_g[pb * 16 + 4  + pdd];
            sg2 = s_g[pb * 16 + 8  + pdd];
            sg3 = s_g[pb * 16 + 12 + pdd];
        }

        // ---- pointwise LSTM cell for (pb, pd)
        float iv = 1.f / (1.f + __expf(-(gi + sg0)));
        float fv = 1.f / (1.f + __expf(-(gf + sg1)));
        float gv = tanhf(gg + sg2);
        float ov = 1.f / (1.f + __expf(-(go + sg3)));
        c = fv * c + iv * gv;
        float h = ov * tanhf(c);

        g_h[pb * D + pd] = h;
        if (t == mylen - 1) g_final[pb * D + pd] = h;

        // ---- grid barrier (128 CTAs co-resident, 1/SM)
        __syncthreads();
        if (tid == 0) {
            __threadfence();
            atomicAdd(&g_arrive, 1u);
            unsigned target = (unsigned)(t + 1) * 128u;
            while (*(volatile unsigned*)&g_arrive < target) { }
            __threadfence();
        }
        __syncthreads();
    }
}

// ---------------- K4: out = final @ w_out^T + b_out --------------------------
__global__ void k4_out(const float* __restrict__ wout, const float* __restrict__ bout,
                       float* __restrict__ out) {
    int b = blockIdx.x;
    int tid = threadIdx.x;
    int o = tid >> 5, lane = tid & 31;
    float s = 0.f;
    for (int k = lane; k < D; k += 32)
        s += g_final[b * D + k] * wout[o * D + k];
#pragma unroll
    for (int off = 16; off; off >>= 1)
        s += __shfl_down_sync(0xffffffffu, s, off);
    if (lane == 0) out[b * 2 + o] = s + bout[o];
}

// ---------------- launcher ---------------------------------------------------
extern "C" void kernel_launch(void* const* d_in, const int* in_sizes, int n_in,
                              void* d_out, int out_size) {
    const int*   seqs    = (const int*)  d_in[0];
    const int*   lengths = (const int*)  d_in[1];
    const float* emb     = (const float*)d_in[2];
    const float* w_ih    = (const float*)d_in[3];
    const float* w_hh    = (const float*)d_in[4];
    const float* w_out   = (const float*)d_in[5];
    const float* b_out   = (const float*)d_in[6];
    float*       out     = (float*)d_out;

    k1_embed<<<B * S, 128>>>(seqs, emb);
    dim3 g2(G4D / 128, (B * S) / 128);   // (16, 128)
    k2_gemm<<<g2, 256>>>(w_ih);
    k_reset<<<1, 1>>>();

    const int K3_SMEM = 131072 + 32768 + 4096;   // 167936 B
    cudaFuncSetAttribute(k3_lstm, cudaFuncAttributeMaxDynamicSharedMemorySize, K3_SMEM);
    k3_lstm<<<128, 256, K3_SMEM>>>(w_hh, lengths);

    k4_out<<<B, 64>>>(w_out, b_out, out);
}

// round 8
// speedup vs baseline: 1.7638x; 1.0121x over previous
#include <cuda_runtime.h>
#include <cuda_bf16.h>
#include <cstdint>

#define VOCAB 20000
#define D     512
#define B     64
#define S     256
#define C     16
#define G4D   (4*D)      // 2048

// ---------------- scratch (device globals; no allocation allowed) ----------
__device__ float g_x[S*B*D];        // [s][b][d]
__device__ float g_gx[S*B*G4D];     // [s][b][4D]
__device__ float g_h[B*D];
__device__ float g_final[B*D];
__device__ unsigned int g_arrive;

// ---------------- helpers ---------------------------------------------------
__device__ __forceinline__ float cvt_tf32(float x) {
    uint32_t u;
    asm("cvt.rna.tf32.f32 %0, %1;" : "=r"(u) : "f"(x));
    return __uint_as_float(u);
}

__device__ __forceinline__ void mma_tf32(float* c, const uint32_t* a, const uint32_t* b) {
    asm volatile(
        "mma.sync.aligned.m16n8k8.row.col.f32.tf32.tf32.f32 "
        "{%0,%1,%2,%3}, {%4,%5,%6,%7}, {%8,%9}, {%0,%1,%2,%3};"
        : "+f"(c[0]), "+f"(c[1]), "+f"(c[2]), "+f"(c[3])
        : "r"(a[0]), "r"(a[1]), "r"(a[2]), "r"(a[3]),
          "r"(b[0]), "r"(b[1]));
}

// packed fp32x2 FMA (Blackwell): acc.lo += a.lo*b.lo ; acc.hi += a.hi*b.hi
__device__ __forceinline__ void fma2(unsigned long long& acc,
                                     unsigned long long a, unsigned long long b) {
    asm("fma.rn.f32x2 %0, %1, %2, %0;" : "+l"(acc) : "l"(a), "l"(b));
}

__device__ __forceinline__ float red2(unsigned long long a) {
    return __uint_as_float((unsigned)a) + __uint_as_float((unsigned)(a >> 32));
}

template<int N> __device__ __forceinline__ void cpwait() {
    asm volatile("cp.async.wait_group %0;" :: "n"(N) : "memory");
}
__device__ __forceinline__ void cpasync16(uint32_t dst, const void* src) {
    asm volatile("cp.async.cg.shared.global [%0], [%1], 16;" :: "r"(dst), "l"(src) : "memory");
}
__device__ __forceinline__ void cpcommit() {
    asm volatile("cp.async.commit_group;" ::: "memory");
}

// ---------------- K1: embedding gather + sum over codes ---------------------
__global__ void k1_embed(const int* __restrict__ seqs, const float* __restrict__ emb) {
    __shared__ int sidx[C];
    int bs  = blockIdx.x;
    int tid = threadIdx.x;
    if (tid < C) sidx[tid] = seqs[bs * C + tid];
    __syncthreads();
    int b = bs >> 8, s = bs & 255;
    float4 acc = make_float4(0.f, 0.f, 0.f, 0.f);
#pragma unroll
    for (int c = 0; c < C; c++) {
        int idx = sidx[c];
        if (idx != VOCAB) {
            float4 v = __ldg(((const float4*)(emb + (size_t)idx * D)) + tid);
            acc.x += v.x; acc.y += v.y; acc.z += v.z; acc.w += v.w;
        }
    }
    *(((float4*)(g_x + (size_t)(s * B + b) * D)) + tid) = acc;
}

// ---------------- K2: gates_x = x @ w_ih^T  (tf32 mma) -----------------------
__global__ void __launch_bounds__(256) k2_gemm(const float* __restrict__ Bw) {
    __shared__ float As[128][36];
    __shared__ float Bs[128][36];

    int tid  = threadIdx.x;
    int warp = tid >> 5, lane = tid & 31;
    int g    = lane >> 2, tig = lane & 3;
    int wm   = (warp & 1) * 64;
    int wn   = (warp >> 1) * 32;
    int bm0  = blockIdx.y * 128;
    int bn0  = blockIdx.x * 128;

    float acc[4][4][4];
#pragma unroll
    for (int mt = 0; mt < 4; mt++)
#pragma unroll
        for (int nt = 0; nt < 4; nt++)
#pragma unroll
            for (int r = 0; r < 4; r++) acc[mt][nt][r] = 0.f;

    for (int kt = 0; kt < D; kt += 32) {
#pragma unroll
        for (int i = 0; i < 4; i++) {
            int f   = tid + i * 256;
            int row = f >> 3, cc = f & 7;
            float4 v = *(const float4*)(g_x + (size_t)(bm0 + row) * D + kt + cc * 4);
            float4 cv = make_float4(cvt_tf32(v.x), cvt_tf32(v.y), cvt_tf32(v.z), cvt_tf32(v.w));
            *(float4*)&As[row][cc * 4] = cv;
            float4 w = *(const float4*)(Bw + (size_t)(bn0 + row) * D + kt + cc * 4);
            float4 cw = make_float4(cvt_tf32(w.x), cvt_tf32(w.y), cvt_tf32(w.z), cvt_tf32(w.w));
            *(float4*)&Bs[row][cc * 4] = cw;
        }
        __syncthreads();

#pragma unroll
        for (int ks = 0; ks < 4; ks++) {
            int k0 = ks * 8;
            uint32_t af[4][4], bf[4][2];
#pragma unroll
            for (int mt = 0; mt < 4; mt++) {
                int m = wm + mt * 16;
                af[mt][0] = __float_as_uint(As[m + g    ][k0 + tig    ]);
                af[mt][1] = __float_as_uint(As[m + g + 8][k0 + tig    ]);
                af[mt][2] = __float_as_uint(As[m + g    ][k0 + tig + 4]);
                af[mt][3] = __float_as_uint(As[m + g + 8][k0 + tig + 4]);
            }
#pragma unroll
            for (int nt = 0; nt < 4; nt++) {
                int n = wn + nt * 8;
                bf[nt][0] = __float_as_uint(Bs[n + g][k0 + tig    ]);
                bf[nt][1] = __float_as_uint(Bs[n + g][k0 + tig + 4]);
            }
#pragma unroll
            for (int mt = 0; mt < 4; mt++)
#pragma unroll
                for (int nt = 0; nt < 4; nt++)
                    mma_tf32(acc[mt][nt], af[mt], bf[nt]);
        }
        __syncthreads();
    }

#pragma unroll
    for (int mt = 0; mt < 4; mt++) {
#pragma unroll
        for (int nt = 0; nt < 4; nt++) {
            int m0 = bm0 + wm + mt * 16 + g;
            int n0 = bn0 + wn + nt * 8 + 2 * tig;
            *(float2*)&g_gx[(size_t)m0 * G4D + n0] =
                make_float2(acc[mt][nt][0], acc[mt][nt][1]);
            *(float2*)&g_gx[(size_t)(m0 + 8) * G4D + n0] =
                make_float2(acc[mt][nt][2], acc[mt][nt][3]);
        }
    }
}

// ---------------- Kreset ------------------------------------------------------
__global__ void k_reset() { g_arrive = 0u; }

// ---------------- K3: persistent LSTM recurrence ------------------------------
// 128 CTAs x 512 threads (4 warps/SMSP for latency hiding).
// CTA owns dims [bid*4, bid*4+4) x 4 gates = 16 rows of W_hh.
// Weights in registers (16 floats/thread): thread = (row = tid&15, ks = tid>>4),
// ks is a k-slice of 16 floats. All 16 lanes of a half-warp read the SAME h
// address (16-way LDS broadcast). h staged GMEM->SMEM via pipelined cp.async.
// Reduction: shfl_xor(16) combines the warp's 2 k-slices; 16 warp-partials per
// (b,row) staged in s_part, summed in phase 2.
extern __shared__ char k3_smem[];

__global__ void __launch_bounds__(512) k3_lstm(const float* __restrict__ whh,
                                               const int*   __restrict__ lengths) {
    float* s_h    = (float*)k3_smem;                       // [64][512]   131072 B
    float* s_part = (float*)(k3_smem + 131072);            // [64][16][16] 65536 B
    float* s_g    = (float*)(k3_smem + 131072 + 65536);    // [64][16]      4096 B
    uint32_t s_h_u32 = (uint32_t)__cvta_generic_to_shared(s_h);

    int tid = threadIdx.x, bid = blockIdx.x;
    int d0  = bid * 4;
    int row = tid & 15;        // row = gate*4 + dd
    int ks  = tid >> 4;        // 0..31: k-slice of 16 floats
    int w   = tid >> 5;        // warp id 0..15
    int lane = tid & 31;

    // ---- weights into registers: w[row][ks*16 .. +16] as 8 packed pairs
    unsigned long long wreg[8];
    {
        int gate = row >> 2, dd = row & 3;
        const float4* wp = (const float4*)(whh + (size_t)(gate * D + d0 + dd) * D + ks * 16);
#pragma unroll
        for (int i = 0; i < 4; i++) {
            float4 v = __ldg(wp + i);
            wreg[2*i]   = ((unsigned long long)__float_as_uint(v.y) << 32) | __float_as_uint(v.x);
            wreg[2*i+1] = ((unsigned long long)__float_as_uint(v.w) << 32) | __float_as_uint(v.z);
        }
    }
    // pointwise mapping: threads < 256 own (pb = tid>>2, pd = d0 + (tid&3))
    int pb = tid >> 2, pdd = tid & 3, pd = d0 + pdd;
    int mylen = (tid < 256) ? lengths[pb] : 0;
    float c = 0.f;

    for (int t = 0; t < S; t++) {
        // prefetch this step's input-projection gates (independent of h)
        float gi = 0.f, gf = 0.f, gg = 0.f, go = 0.f;
        if (tid < 256) {
            size_t gxbase = ((size_t)(t * B + pb)) * G4D + pd;
            gi = __ldg(g_gx + gxbase);
            gf = __ldg(g_gx + gxbase + D);
            gg = __ldg(g_gx + gxbase + 2 * D);
            go = __ldg(g_gx + gxbase + 3 * D);
        }

        float sg0 = 0.f, sg1 = 0.f, sg2 = 0.f, sg3 = 0.f;
        if (t > 0) {
            // ---- stage h: 8192 x 16B chunks (linear), 4 commit groups of 16 b
#pragma unroll
            for (int grp = 0; grp < 4; grp++) {
#pragma unroll
                for (int jj = 0; jj < 4; jj++) {
                    int idx = tid + 512 * (grp * 4 + jj);
                    cpasync16(s_h_u32 + idx * 16, (const char*)g_h + (size_t)idx * 16);
                }
                cpcommit();
            }

            // ---- dot over 4 pipelined b-blocks of 16
            auto dotblock = [&](int b0) {
#pragma unroll 2
                for (int bb = 0; bb < 16; bb++) {
                    int b = b0 + bb;
                    const ulonglong2* hp = (const ulonglong2*)(s_h + b * 512 + ks * 16);
                    unsigned long long a0 = 0, a1 = 0;
#pragma unroll
                    for (int i = 0; i < 4; i++) {
                        ulonglong2 hv = hp[i];           // 16-way broadcast
                        fma2(a0, hv.x, wreg[2*i]);
                        fma2(a1, hv.y, wreg[2*i+1]);
                    }
                    float s = red2(a0) + red2(a1);
                    s += __shfl_xor_sync(0xffffffffu, s, 16);  // combine warp's 2 k-slices
                    if (lane < 16)
                        s_part[b * 256 + w * 16 + row] = s;    // conflict-free 16 floats
                }
            };
            cpwait<3>(); __syncthreads(); dotblock(0);
            cpwait<2>(); __syncthreads(); dotblock(16);
            cpwait<1>(); __syncthreads(); dotblock(32);
            cpwait<0>(); __syncthreads(); dotblock(48);
            __syncthreads();

            // ---- phase 2: sum the 16 warp-partials; thread = (b2, 2 rows)
            {
                int b2 = tid >> 3, rr = (tid & 7) * 2;
                float2 a2 = make_float2(0.f, 0.f);
#pragma unroll
                for (int w2 = 0; w2 < 16; w2++) {
                    float2 v = *(const float2*)(s_part + b2 * 256 + w2 * 16 + rr);
                    a2.x += v.x; a2.y += v.y;
                }
                *(float2*)(s_g + b2 * 16 + rr) = a2;   // [b][gate*4+dd]
            }
            __syncthreads();
            if (tid < 256) {
                sg0 = s_g[pb * 16 + 0  + pdd];
                sg1 = s_g[pb * 16 + 4  + pdd];
                sg2 = s_g[pb * 16 + 8  + pdd];
                sg3 = s_g[pb * 16 + 12 + pdd];
            }
        }

        // ---- pointwise LSTM cell for (pb, pd)
        if (tid < 256) {
            float iv = 1.f / (1.f + __expf(-(gi + sg0)));
            float fv = 1.f / (1.f + __expf(-(gf + sg1)));
            float gv = tanhf(gg + sg2);
            float ov = 1.f / (1.f + __expf(-(go + sg3)));
            c = fv * c + iv * gv;
            float h = ov * tanhf(c);

            g_h[pb * D + pd] = h;
            if (t == mylen - 1) g_final[pb * D + pd] = h;
        }

        // ---- grid barrier (128 CTAs co-resident, 1/SM)
        __syncthreads();
        if (tid == 0) {
            __threadfence();
            atomicAdd(&g_arrive, 1u);
            unsigned target = (unsigned)(t + 1) * 128u;
            while (*(volatile unsigned*)&g_arrive < target) { }
            __threadfence();
        }
        __syncthreads();
    }
}

// ---------------- K4: out = final @ w_out^T + b_out --------------------------
__global__ void k4_out(const float* __restrict__ wout, const float* __restrict__ bout,
                       float* __restrict__ out) {
    int b = blockIdx.x;
    int tid = threadIdx.x;
    int o = tid >> 5, lane = tid & 31;
    float s = 0.f;
    for (int k = lane; k < D; k += 32)
        s += g_final[b * D + k] * wout[o * D + k];
#pragma unroll
    for (int off = 16; off; off >>= 1)
        s += __shfl_down_sync(0xffffffffu, s, off);
    if (lane == 0) out[b * 2 + o] = s + bout[o];
}

// ---------------- launcher ---------------------------------------------------
extern "C" void kernel_launch(void* const* d_in, const int* in_sizes, int n_in,
                              void* d_out, int out_size) {
    const int*   seqs    = (const int*)  d_in[0];
    const int*   lengths = (const int*)  d_in[1];
    const float* emb     = (const float*)d_in[2];
    const float* w_ih    = (const float*)d_in[3];
    const float* w_hh    = (const float*)d_in[4];
    const float* w_out   = (const float*)d_in[5];
    const float* b_out   = (const float*)d_in[6];
    float*       out     = (float*)d_out;

    k1_embed<<<B * S, 128>>>(seqs, emb);
    dim3 g2(G4D / 128, (B * S) / 128);   // (16, 128)
    k2_gemm<<<g2, 256>>>(w_ih);
    k_reset<<<1, 1>>>();

    const int K3_SMEM = 131072 + 65536 + 4096;   // 200704 B
    cudaFuncSetAttribute(k3_lstm, cudaFuncAttributeMaxDynamicSharedMemorySize, K3_SMEM);
    k3_lstm<<<128, 512, K3_SMEM>>>(w_hh, lengths);

    k4_out<<<B, 64>>>(w_out, b_out, out);
}